// round 15
// baseline (speedup 1.0000x reference)
#include <cuda_runtime.h>
#include <math.h>

typedef unsigned long long ull;

constexpr int NAT = 64;
constexpr int NE  = 512;
constexpr int NA  = 65;
constexpr int NUMEL = 10;
constexpr int CH  = 256;    // chunk width (edges)
constexpr int WCP = 260;    // Wc pitch (floats)
constexpr int HP  = 68;     // Hs pitch
constexpr int KP  = 68;     // Km pitch (16B-aligned rows)
constexpr int FP  = 68;     // Fm pitch
constexpr int NTH = 384;    // 12 warps

// ---- shared memory byte offsets ----
constexpr int OFF_WC  = 0;                       // float Wc[65][260]
constexpr int OFF_KM  = OFF_WC;                  // float Km[65][68]  (aliases Wc)
constexpr int OFF_FM  = OFF_WC + 65*KP*4 + 16;   // float Fm[65][68]  (aliases Wc, after Km)
constexpr int OFF_AS  = OFF_WC + 65*WCP*4;       // float As[64][64]
constexpr int OFF_HS  = OFF_AS + 64*64*4;        // float Hs[65][68]
constexpr int OFF_SA  = OFF_HS + 65*HP*4;        // float sa[512]
constexpr int OFF_PX  = OFF_SA + 2048;
constexpr int OFF_PY  = OFF_PX + 256;
constexpr int OFF_PZ  = OFF_PY + 256;
constexpr int OFF_EN  = OFF_PZ + 256;
constexpr int OFF_DG  = OFF_EN + 256;
constexpr int OFF_RR  = OFF_DG + 256;
constexpr int OFF_RF  = OFF_RR + 256;            // float rf[68]
constexpr int OFF_DI  = OFF_RF + 272;            // float dinv[68]
constexpr int OFF_PH  = OFF_DI + 272;            // int pivhist[68]
constexpr int SMEM_BYTES = OFF_PH + 272;         // ~104 KB -> 2 CTAs/SM

static_assert(OFF_FM + 65*FP*4 <= OFF_AS, "Fm must fit in Wc region after Km");

__device__ __forceinline__ ull ffma2(ull a, ull b, ull c) {
    ull d; asm("fma.rn.f32x2 %0, %1, %2, %3;" : "=l"(d) : "l"(a), "l"(b), "l"(c)); return d;
}
__device__ __forceinline__ ull fadd2(ull a, ull b) {
    ull d; asm("add.rn.f32x2 %0, %1, %2;" : "=l"(d) : "l"(a), "l"(b)); return d;
}
__device__ __forceinline__ float2 unpack2(ull v) {
    float2 f; asm("mov.b64 {%0,%1}, %2;" : "=f"(f.x), "=f"(f.y) : "l"(v)); return f;
}
__device__ __forceinline__ ull dup2(float f) {
    ull d; asm("mov.b64 %0, {%1, %1};" : "=l"(d) : "f"(f)); return d;
}
// monotone packed key: |v| in top 25 bits, row in low 7
__device__ __forceinline__ unsigned int pivkey(float v, int row) {
    return (__float_as_uint(fabsf(v)) & 0xFFFFFF80u) | (unsigned int)row;
}
// warp-collective pivot select over 65 rows held as (v0:lane, v1:lane+32, v2:row64@lane0)
__device__ __forceinline__ void sel_piv(float v0, float v1, float v2,
                                        bool f0, bool f1, bool f2,
                                        int lane, int& prow, float& dv) {
    unsigned int key = f0 ? 0u : pivkey(v0, lane);
    unsigned int k1  = f1 ? 0u : pivkey(v1, lane + 32);
    if (k1 > key) key = k1;
    if (lane == 0 && !f2) { unsigned int k2 = pivkey(v2, 64); if (k2 > key) key = k2; }
    #pragma unroll
    for (int o = 16; o; o >>= 1) {
        unsigned int ov = __shfl_xor_sync(0xffffffffu, key, o);
        if (ov > key) key = ov;
    }
    prow = (int)(key & 0x7Fu);
    float src = (prow < 32) ? v0 : ((prow < 64) ? v1 : v2);
    float pval = __shfl_sync(0xffffffffu, src, prow & 31);
    dv = 1.0f / pval;
}

__global__ __launch_bounds__(NTH, 2)
void cheq_kernel(const float* __restrict__ positions,
                 const float* __restrict__ T,
                 const float* __restrict__ eneg,
                 const float* __restrict__ node_attrs,
                 const float* __restrict__ total_charge,
                 const float* __restrict__ hardness,
                 const float* __restrict__ cov_radii,
                 const int*   __restrict__ atomic_numbers,
                 const int*   __restrict__ edge_index,
                 float* __restrict__ out)
{
    extern __shared__ __align__(16) unsigned char sm[];
    float* Wc  = (float*)(sm + OFF_WC);
    float* Km  = (float*)(sm + OFF_KM);
    float* Fm  = (float*)(sm + OFF_FM);
    float* As  = (float*)(sm + OFF_AS);
    float* Hs  = (float*)(sm + OFF_HS);
    float* sa  = (float*)(sm + OFF_SA);
    float* px  = (float*)(sm + OFF_PX);
    float* py  = (float*)(sm + OFF_PY);
    float* pz  = (float*)(sm + OFF_PZ);
    float* ens = (float*)(sm + OFF_EN);
    float* dgs = (float*)(sm + OFF_DG);
    float* rrs = (float*)(sm + OFF_RR);
    float* rf  = (float*)(sm + OFF_RF);
    float* dinv= (float*)(sm + OFF_DI);
    int*   pivhist = (int*)(sm + OFF_PH);

    const int mol = blockIdx.x;
    const int t = threadIdx.x;
    const int lane = t & 31;
    const int w = t >> 5;
    const float* Tm = T + (size_t)mol * (NAT * NE);
    const float* pm = positions + mol * NAT * 3;
    const int* eim = edge_index + mol * 2 * NE;
    const float q = total_charge[mol];

    // ---- per-atom small loads ----
    if (t < NAT) {
        px[t] = pm[3*t+0]; py[t] = pm[3*t+1]; pz[t] = pm[3*t+2];
        ens[t] = eneg[mol * NAT + t];
        float r = cov_radii[atomic_numbers[mol * NAT + t]];
        rrs[t] = r * r;
        const float* na = node_attrs + (size_t)(mol * NAT + t) * NUMEL;
        float best = na[0]; int bi = 0;
        #pragma unroll
        for (int j = 1; j < NUMEL; j++) { float v = na[j]; if (v > best) { best = v; bi = j; } }
        dgs[t] = hardness[bi] + 0.5641895835477563f / r;
    }
    __syncthreads();

    // ---- A matrix (64x64, symmetric): lower triangle, mirrored store ----
    for (int p = t; p < 2080; p += NTH) {
        int i = (int)((sqrtf(8.0f * p + 1.0f) - 1.0f) * 0.5f);
        while ((i + 1) * (i + 2) / 2 <= p) ++i;
        while (i * (i + 1) / 2 > p) --i;
        int j = p - i * (i + 1) / 2;
        float v;
        if (i == j) v = dgs[i];
        else {
            float dx = px[i]-px[j], dy = py[i]-py[j], dz = pz[i]-pz[j];
            float d = sqrtf(dx*dx + dy*dy + dz*dz);
            float arg = d * rsqrtf(2.0f * (rrs[i] + rrs[j]));
            v = erff(arg) / d;
        }
        As[i * 64 + j] = v;
        As[j * 64 + i] = v;
    }

    // ---- edges: sa[e] = sqrt(1/cut), cancellation-free ----
    for (int e = t; e < NE; e += NTH) {
        int a0 = eim[e], a1 = eim[NE + e];
        float dx = px[a0]-px[a1], dy = py[a0]-py[a1], dz = pz[a0]-pz[a1];
        float ed = sqrtf(dx*dx + dy*dy + dz*dz);
        float th = 0.15707963267948966f * ed;
        float sh = sinf(0.5f * th);
        float ct = cosf(th);
        float dv = ct / (2.0f * sh * sh);
        dv = fmaxf(dv, 1e-30f);
        sa[e] = sqrtf(dv);
    }
    __syncthreads();

    // ---- syrk tile geometry (91 triangular 5x5 tiles; 12 warps x 4 groups x 2 rounds) ----
    const int g  = (lane >> 3);
    const int l8 = lane & 7;
    int tiR[2], tjR[2]; bool actR[2];
    #pragma unroll
    for (int r = 0; r < 2; r++) {
        int p = r * 48 + w * 4 + g;
        actR[r] = (p < 91);
        int pp = actR[r] ? p : 0;
        int ti = (int)((sqrtf(8.0f * pp + 1.0f) - 1.0f) * 0.5f);
        while ((ti + 1) * (ti + 2) / 2 <= pp) ++ti;
        while (ti * (ti + 1) / 2 > pp) --ti;
        tiR[r] = ti; tjR[r] = pp - ti * (ti + 1) / 2;
    }

    // ---- chunk loop: H = W W^T ----
    for (int c = 0; c < 2; c++) {
        const int base = c * CH;
        for (int idx = t; idx < 64 * 64; idx += NTH) {
            int a = idx >> 6, e = (idx & 63) * 4;
            float4 v  = *(const float4*)(Tm + a * NE + base + e);
            float4 s4 = *(const float4*)(sa + base + e);
            v.x *= s4.x; v.y *= s4.y; v.z *= s4.z; v.w *= s4.w;
            *(float4*)(Wc + a * WCP + e) = v;
        }
        if (t < 64) *(float4*)(Wc + 64 * WCP + 4*t) = *(const float4*)(sa + base + 4*t);
        __syncthreads();

        #pragma unroll
        for (int r = 0; r < 2; r++) {
            const float* Wa = Wc + (tiR[r] * 5) * WCP;
            const float* Wb = Wc + (tjR[r] * 5) * WCP;
            const bool diag = (tiR[r] == tjR[r]);
            ull acc[25];
            #pragma unroll
            for (int m = 0; m < 25; m++) acc[m] = 0ull;
            for (int e = 4 * l8; e < CH; e += 32) {
                ulonglong2 av[5];
                #pragma unroll
                for (int i = 0; i < 5; i++)
                    av[i] = *(const ulonglong2*)(Wa + i * WCP + e);
                #pragma unroll
                for (int j = 0; j < 5; j++) {
                    ulonglong2 bv = diag ? av[j] : *(const ulonglong2*)(Wb + j * WCP + e);
                    #pragma unroll
                    for (int i = 0; i < 5; i++) {
                        acc[i*5+j] = ffma2(av[i].x, bv.x, acc[i*5+j]);
                        acc[i*5+j] = ffma2(av[i].y, bv.y, acc[i*5+j]);
                    }
                }
            }
            #pragma unroll
            for (int m = 0; m < 25; m++) {
                acc[m] = fadd2(acc[m], __shfl_down_sync(0xffffffffu, acc[m], 4));
                acc[m] = fadd2(acc[m], __shfl_down_sync(0xffffffffu, acc[m], 2));
                acc[m] = fadd2(acc[m], __shfl_down_sync(0xffffffffu, acc[m], 1));
            }
            if (actR[r] && l8 == 0) {
                int ti = tiR[r], tj = tjR[r];
                #pragma unroll
                for (int i = 0; i < 5; i++)
                    #pragma unroll
                    for (int j = 0; j < 5; j++) {
                        float2 f = unpack2(acc[i*5+j]);
                        float v = f.x + f.y;
                        int lo = (ti*5+i) * HP + (tj*5+j);
                        if (c == 0) Hs[lo] = v; else Hs[lo] += v;
                        if (ti != tj) {
                            int up = (tj*5+j) * HP + (ti*5+i);
                            if (c == 0) Hs[up] = v; else Hs[up] += v;
                        }
                    }
            }
        }
        __syncthreads();
    }

    // ---- K = I + H*C; rhs col 65 = -H*u (fp64); col 64 = delta - H col64 ----
    for (int a = w; a < NA; a += 12) {
        const float* Hr = Hs + a * HP;
        double acc = 0.0;
        for (int k2 = lane; k2 < NA; k2 += 32) {
            float uk = (k2 < 64) ? ens[k2] : q;
            acc += (double)Hr[k2] * (double)uk;
        }
        #pragma unroll
        for (int off = 16; off; off >>= 1) acc += __shfl_down_sync(0xffffffffu, acc, off);
        if (lane == 0) Km[a * KP + 65] = (float)(-acc);
    }
    if (t < NA)
        Km[t * KP + 64] = ((t == 64) ? 1.0f : 0.0f) - Hs[t * HP + 64];
    {
        const int half = lane >> 4;
        const int c0 = (lane & 15) * 4;
        #pragma unroll
        for (int pass = 0; pass < 3; pass++) {
            int a = pass * 24 + w * 2 + half;
            if (a < NA) {
                const float* Hr = Hs + a * HP;
                ull acc0 = 0ull, acc1 = 0ull;
                #pragma unroll 4
                for (int k4 = 0; k4 < 16; k4++) {
                    float4 hv = *(const float4*)(Hr + k4 * 4);
                    ulonglong2 a0 = *(const ulonglong2*)(As + (k4*4+0) * 64 + c0);
                    ulonglong2 a1 = *(const ulonglong2*)(As + (k4*4+1) * 64 + c0);
                    ulonglong2 a2 = *(const ulonglong2*)(As + (k4*4+2) * 64 + c0);
                    ulonglong2 a3 = *(const ulonglong2*)(As + (k4*4+3) * 64 + c0);
                    ull h0 = dup2(hv.x), h1 = dup2(hv.y), h2 = dup2(hv.z), h3 = dup2(hv.w);
                    acc0 = ffma2(h0, a0.x, acc0); acc1 = ffma2(h0, a0.y, acc1);
                    acc0 = ffma2(h1, a1.x, acc0); acc1 = ffma2(h1, a1.y, acc1);
                    acc0 = ffma2(h2, a2.x, acc0); acc1 = ffma2(h2, a2.y, acc1);
                    acc0 = ffma2(h3, a3.x, acc0); acc1 = ffma2(h3, a3.y, acc1);
                }
                float2 f0 = unpack2(acc0), f1 = unpack2(acc1);
                float4 v;
                v.x = f0.x + ((a == c0+0) ? 1.0f : 0.0f);
                v.y = f0.y + ((a == c0+1) ? 1.0f : 0.0f);
                v.z = f1.x + ((a == c0+2) ? 1.0f : 0.0f);
                v.w = f1.y + ((a == c0+3) ? 1.0f : 0.0f);
                *(float4*)(Km + a * KP + c0) = v;
            }
        }
    }
    __syncthreads();

    // ---- Gauss-Jordan, paired pivots: 2 eliminations per barrier interval ----
    // Column j owned by warp (j>>1)%12; warp-local slots c: pair pp -> cols
    // j = 2*(w + 12*pp) + (c&1). 33 pairs; warps 0..8 own 3, warps 9..11 own 2.
    {
        float cv0[6], cv1[6], cv2[6];
        #pragma unroll
        for (int c = 0; c < 6; c++) {
            cv0[c] = 0.f; cv1[c] = 0.f; cv2[c] = 0.f;
            int j = 2 * (w + 12 * (c >> 1)) + (c & 1);
            if (j < 66) {
                cv0[c] = Km[lane * KP + j];
                cv1[c] = Km[(lane + 32) * KP + j];
                if (lane == 0) cv2[c] = Km[64 * KP + j];
            }
        }
        bool piv0 = false, piv1 = false, piv2 = false;

        // bootstrap: warp 0 owns pair 0 (cols 0,1) -> pivots 0 and 1
        if (w == 0) {
            int pr; float dv;
            sel_piv(cv0[0], cv1[0], cv2[0], false, false, false, lane, pr, dv);
            if (lane == 0) { pivhist[0] = pr; dinv[0] = dv; }
            Fm[lane] = cv0[0]; Fm[lane + 32] = cv1[0];
            if (lane == 0) Fm[64] = cv2[0];
            float m0 = cv0[0] * dv, m1 = cv1[0] * dv, m2 = cv2[0] * dv;
            if (lane == pr)      m0 = 0.f;
            if (lane + 32 == pr) m1 = 0.f;
            if (pr == 64)        m2 = 0.f;
            float s = (pr < 32) ? cv0[1] : ((pr < 64) ? cv1[1] : cv2[1]);
            float pv = __shfl_sync(0xffffffffu, s, pr & 31);
            cv0[1] = fmaf(-m0, pv, cv0[1]);
            cv1[1] = fmaf(-m1, pv, cv1[1]);
            cv2[1] = fmaf(-m2, pv, cv2[1]);
            bool g0 = (lane == pr), g1 = (lane + 32 == pr), g2 = (pr == 64);
            int pr2; float dv2;
            sel_piv(cv0[1], cv1[1], cv2[1], g0, g1, g2, lane, pr2, dv2);
            if (lane == 0) { pivhist[1] = pr2; dinv[1] = dv2; }
            Fm[FP + lane] = cv0[1]; Fm[FP + lane + 32] = cv1[1];
            if (lane == 0) Fm[FP + 64] = cv2[1];
        }
        __syncthreads();

        for (int p = 0; p < 32; p++) {
            const int k0 = 2 * p, k1 = 2 * p + 1;
            const int pk0 = pivhist[k0], pk1 = pivhist[k1];
            const float dk0 = dinv[k0], dk1 = dinv[k1];
            const float* F0 = Fm + k0 * FP;
            const float* F1 = Fm + k1 * FP;
            float a0 = F0[lane] * dk0, a1 = F0[lane + 32] * dk0, a2 = F0[64] * dk0;
            float b0 = F1[lane] * dk1, b1 = F1[lane + 32] * dk1, b2 = F1[64] * dk1;
            if (lane == pk0)      a0 = 0.f;
            if (lane + 32 == pk0) a1 = 0.f;
            if (pk0 == 64)        a2 = 0.f;
            if (lane == pk1)      b0 = 0.f;
            if (lane + 32 == pk1) b1 = 0.f;
            if (pk1 == 64)        b2 = 0.f;
            piv0 |= (lane == pk0) | (lane == pk1);
            piv1 |= (lane + 32 == pk0) | (lane + 32 == pk1);
            piv2 |= (pk0 == 64) | (pk1 == 64);
            #pragma unroll
            for (int c = 0; c < 6; c++) {
                int j = 2 * (w + 12 * (c >> 1)) + (c & 1);
                if (j < 66 && j > k1) {          // warp-uniform predicate
                    float s0 = (pk0 < 32) ? cv0[c] : ((pk0 < 64) ? cv1[c] : cv2[c]);
                    float pv0 = __shfl_sync(0xffffffffu, s0, pk0 & 31);
                    cv0[c] = fmaf(-a0, pv0, cv0[c]);
                    cv1[c] = fmaf(-a1, pv0, cv1[c]);
                    cv2[c] = fmaf(-a2, pv0, cv2[c]);
                    float s1 = (pk1 < 32) ? cv0[c] : ((pk1 < 64) ? cv1[c] : cv2[c]);
                    float pv1 = __shfl_sync(0xffffffffu, s1, pk1 & 31);
                    cv0[c] = fmaf(-b0, pv1, cv0[c]);
                    cv1[c] = fmaf(-b1, pv1, cv1[c]);
                    cv2[c] = fmaf(-b2, pv1, cv2[c]);
                }
            }
            const int P = p + 1;                  // owner of next pair
            if (w == (P % 12)) {
                const int ca = 2 * (P / 12), cb = ca + 1;
                const int nk0 = 2 * P, nk1 = 2 * P + 1;
                int pr; float dv;
                sel_piv(cv0[ca], cv1[ca], cv2[ca], piv0, piv1, piv2, lane, pr, dv);
                if (lane == 0) { pivhist[nk0] = pr; dinv[nk0] = dv; }
                float m0 = cv0[ca] * dv, m1 = cv1[ca] * dv, m2 = cv2[ca] * dv;
                if (lane == pr)      m0 = 0.f;
                if (lane + 32 == pr) m1 = 0.f;
                if (pr == 64)        m2 = 0.f;
                float s = (pr < 32) ? cv0[cb] : ((pr < 64) ? cv1[cb] : cv2[cb]);
                float pv = __shfl_sync(0xffffffffu, s, pr & 31);
                float u0 = fmaf(-m0, pv, cv0[cb]);
                float u1 = fmaf(-m1, pv, cv1[cb]);
                float u2 = fmaf(-m2, pv, cv2[cb]);
                cv0[cb] = u0; cv1[cb] = u1; cv2[cb] = u2;
                if (P < 32) {
                    Fm[nk0 * FP + lane] = cv0[ca];
                    Fm[nk0 * FP + lane + 32] = cv1[ca];
                    if (lane == 0) Fm[nk0 * FP + 64] = cv2[ca];
                    bool g0 = piv0 | (lane == pr);
                    bool g1 = piv1 | (lane + 32 == pr);
                    bool g2 = piv2 | (pr == 64);
                    int pr2; float dv2;
                    sel_piv(u0, u1, u2, g0, g1, g2, lane, pr2, dv2);
                    if (lane == 0) { pivhist[nk1] = pr2; dinv[nk1] = dv2; }
                    Fm[nk1 * FP + lane] = u0;
                    Fm[nk1 * FP + lane + 32] = u1;
                    if (lane == 0) Fm[nk1 * FP + 64] = u2;
                } else {
                    // pair 32 = (col 64, rhs col 65): pivot 64 applied, rhs complete
                    rf[lane] = u0;
                    rf[lane + 32] = u1;
                    if (lane == 0) rf[64] = u2;
                }
            }
            __syncthreads();
        }
    }

    // ---- direct solution (Jordan; no back-substitution, no refinement) ----
    if (t < NAT) out[mol * NAT + t] = rf[pivhist[t]] * dinv[t];
}

extern "C" void kernel_launch(void* const* d_in, const int* in_sizes, int n_in,
                              void* d_out, int out_size)
{
    const float* positions      = (const float*)d_in[0];
    const float* T              = (const float*)d_in[1];
    const float* eneg           = (const float*)d_in[2];
    const float* node_attrs     = (const float*)d_in[3];
    const float* total_charge   = (const float*)d_in[4];
    const float* hardness       = (const float*)d_in[6];
    const float* cov_radii      = (const float*)d_in[7];
    const int*   atomic_numbers = (const int*)d_in[8];
    const int*   edge_index     = (const int*)d_in[9];
    float* out = (float*)d_out;

    int B = in_sizes[4];
    cudaFuncSetAttribute(cheq_kernel, cudaFuncAttributeMaxDynamicSharedMemorySize, SMEM_BYTES);
    cheq_kernel<<<B, NTH, SMEM_BYTES>>>(positions, T, eneg, node_attrs, total_charge,
                                        hardness, cov_radii, atomic_numbers, edge_index, out);
}

// round 16
// speedup vs baseline: 1.1035x; 1.1035x over previous
#include <cuda_runtime.h>
#include <math.h>

typedef unsigned long long ull;

constexpr int NAT = 64;
constexpr int NE  = 512;
constexpr int NA  = 65;
constexpr int NUMEL = 10;
constexpr int CH  = 256;    // chunk width (edges)
constexpr int WCP = 260;    // Wc pitch (floats)
constexpr int HP  = 68;     // Hs pitch
constexpr int KP  = 68;     // Km pitch (16B-aligned rows)
constexpr int FP  = 68;     // Fm pitch
constexpr int NTH = 384;    // 12 warps

// ---- shared memory byte offsets ----
constexpr int OFF_WC  = 0;                       // float Wc[65][260]
constexpr int OFF_KM  = OFF_WC;                  // float Km[65][68]  (aliases Wc)
constexpr int OFF_FM  = OFF_WC + 65*KP*4 + 16;   // float Fm[65][68]  (aliases Wc, after Km)
constexpr int OFF_AS  = OFF_WC + 65*WCP*4;       // float As[64][64]
constexpr int OFF_HS  = OFF_AS + 64*64*4;        // float Hs[65][68]
constexpr int OFF_SA  = OFF_HS + 65*HP*4;        // float sa[512]
constexpr int OFF_PX  = OFF_SA + 2048;
constexpr int OFF_PY  = OFF_PX + 256;
constexpr int OFF_PZ  = OFF_PY + 256;
constexpr int OFF_EN  = OFF_PZ + 256;
constexpr int OFF_DG  = OFF_EN + 256;
constexpr int OFF_RR  = OFF_DG + 256;
constexpr int OFF_RF  = OFF_RR + 256;            // float rf[68]
constexpr int OFF_DI  = OFF_RF + 272;            // float dinv[68]
constexpr int OFF_PH  = OFF_DI + 272;            // int pivhist[68]
constexpr int SMEM_BYTES = OFF_PH + 272;         // ~104 KB -> 2 CTAs/SM

static_assert(OFF_FM + 65*FP*4 <= OFF_AS, "Fm must fit in Wc region after Km");

__device__ __forceinline__ ull ffma2(ull a, ull b, ull c) {
    ull d; asm("fma.rn.f32x2 %0, %1, %2, %3;" : "=l"(d) : "l"(a), "l"(b), "l"(c)); return d;
}
__device__ __forceinline__ ull fadd2(ull a, ull b) {
    ull d; asm("add.rn.f32x2 %0, %1, %2;" : "=l"(d) : "l"(a), "l"(b)); return d;
}
__device__ __forceinline__ float2 unpack2(ull v) {
    float2 f; asm("mov.b64 {%0,%1}, %2;" : "=f"(f.x), "=f"(f.y) : "l"(v)); return f;
}
__device__ __forceinline__ ull dup2(float f) {
    ull d; asm("mov.b64 %0, {%1, %1};" : "=l"(d) : "f"(f)); return d;
}
// monotone packed key: |v| in top 25 bits, row in low 7
__device__ __forceinline__ unsigned int pivkey(float v, int row) {
    return (__float_as_uint(fabsf(v)) & 0xFFFFFF80u) | (unsigned int)row;
}

__global__ __launch_bounds__(NTH, 2)
void cheq_kernel(const float* __restrict__ positions,
                 const float* __restrict__ T,
                 const float* __restrict__ eneg,
                 const float* __restrict__ node_attrs,
                 const float* __restrict__ total_charge,
                 const float* __restrict__ hardness,
                 const float* __restrict__ cov_radii,
                 const int*   __restrict__ atomic_numbers,
                 const int*   __restrict__ edge_index,
                 float* __restrict__ out)
{
    extern __shared__ __align__(16) unsigned char sm[];
    float* Wc  = (float*)(sm + OFF_WC);
    float* Km  = (float*)(sm + OFF_KM);
    float* Fm  = (float*)(sm + OFF_FM);
    float* As  = (float*)(sm + OFF_AS);
    float* Hs  = (float*)(sm + OFF_HS);
    float* sa  = (float*)(sm + OFF_SA);
    float* px  = (float*)(sm + OFF_PX);
    float* py  = (float*)(sm + OFF_PY);
    float* pz  = (float*)(sm + OFF_PZ);
    float* ens = (float*)(sm + OFF_EN);
    float* dgs = (float*)(sm + OFF_DG);
    float* rrs = (float*)(sm + OFF_RR);
    float* rf  = (float*)(sm + OFF_RF);
    float* dinv= (float*)(sm + OFF_DI);
    int*   pivhist = (int*)(sm + OFF_PH);

    const int mol = blockIdx.x;
    const int t = threadIdx.x;
    const int lane = t & 31;
    const int w = t >> 5;
    const float* Tm = T + (size_t)mol * (NAT * NE);
    const float* pm = positions + mol * NAT * 3;
    const int* eim = edge_index + mol * 2 * NE;
    const float q = total_charge[mol];

    // ---- per-atom small loads ----
    if (t < NAT) {
        px[t] = pm[3*t+0]; py[t] = pm[3*t+1]; pz[t] = pm[3*t+2];
        ens[t] = eneg[mol * NAT + t];
        float r = cov_radii[atomic_numbers[mol * NAT + t]];
        rrs[t] = r * r;
        const float* na = node_attrs + (size_t)(mol * NAT + t) * NUMEL;
        float best = na[0]; int bi = 0;
        #pragma unroll
        for (int j = 1; j < NUMEL; j++) { float v = na[j]; if (v > best) { best = v; bi = j; } }
        dgs[t] = hardness[bi] + 0.5641895835477563f / r;
    }
    __syncthreads();

    // ---- A matrix (64x64, symmetric): lower triangle only, mirrored store ----
    for (int p = t; p < 2080; p += NTH) {        // 2080 = 64*65/2
        int i = (int)((sqrtf(8.0f * p + 1.0f) - 1.0f) * 0.5f);
        while ((i + 1) * (i + 2) / 2 <= p) ++i;
        while (i * (i + 1) / 2 > p) --i;
        int j = p - i * (i + 1) / 2;
        float v;
        if (i == j) v = dgs[i];
        else {
            float dx = px[i]-px[j], dy = py[i]-py[j], dz = pz[i]-pz[j];
            float d = sqrtf(dx*dx + dy*dy + dz*dz);
            float arg = d * rsqrtf(2.0f * (rrs[i] + rrs[j]));
            v = erff(arg) / d;
        }
        As[i * 64 + j] = v;
        As[j * 64 + i] = v;
    }

    // ---- edges: sa[e] = sqrt(1/cut), cancellation-free ----
    for (int e = t; e < NE; e += NTH) {
        int a0 = eim[e], a1 = eim[NE + e];
        float dx = px[a0]-px[a1], dy = py[a0]-py[a1], dz = pz[a0]-pz[a1];
        float ed = sqrtf(dx*dx + dy*dy + dz*dz);
        float th = 0.15707963267948966f * ed;
        float sh = sinf(0.5f * th);
        float ct = cosf(th);
        float dv = ct / (2.0f * sh * sh);
        dv = fmaxf(dv, 1e-30f);
        sa[e] = sqrtf(dv);
    }
    __syncthreads();

    // ---- syrk tile geometry (91 triangular 5x5 tiles; 12 warps x 4 groups x 2 rounds) ----
    const int g  = (lane >> 3);
    const int l8 = lane & 7;
    int tiR[2], tjR[2]; bool actR[2];
    #pragma unroll
    for (int r = 0; r < 2; r++) {
        int p = r * 48 + w * 4 + g;
        actR[r] = (p < 91);
        int pp = actR[r] ? p : 0;
        int ti = (int)((sqrtf(8.0f * pp + 1.0f) - 1.0f) * 0.5f);
        while ((ti + 1) * (ti + 2) / 2 <= pp) ++ti;
        while (ti * (ti + 1) / 2 > pp) --ti;
        tiR[r] = ti; tjR[r] = pp - ti * (ti + 1) / 2;
    }

    // ---- chunk loop: H = W W^T ----
    for (int c = 0; c < 2; c++) {
        const int base = c * CH;
        for (int idx = t; idx < 64 * 64; idx += NTH) {
            int a = idx >> 6, e = (idx & 63) * 4;
            float4 v  = *(const float4*)(Tm + a * NE + base + e);
            float4 s4 = *(const float4*)(sa + base + e);
            v.x *= s4.x; v.y *= s4.y; v.z *= s4.z; v.w *= s4.w;
            *(float4*)(Wc + a * WCP + e) = v;
        }
        if (t < 64) *(float4*)(Wc + 64 * WCP + 4*t) = *(const float4*)(sa + base + 4*t);
        __syncthreads();

        #pragma unroll
        for (int r = 0; r < 2; r++) {
            const float* Wa = Wc + (tiR[r] * 5) * WCP;
            const float* Wb = Wc + (tjR[r] * 5) * WCP;
            const bool diag = (tiR[r] == tjR[r]);
            ull acc[25];
            #pragma unroll
            for (int m = 0; m < 25; m++) acc[m] = 0ull;
            for (int e = 4 * l8; e < CH; e += 32) {
                ulonglong2 av[5];
                #pragma unroll
                for (int i = 0; i < 5; i++)
                    av[i] = *(const ulonglong2*)(Wa + i * WCP + e);
                #pragma unroll
                for (int j = 0; j < 5; j++) {
                    ulonglong2 bv = diag ? av[j] : *(const ulonglong2*)(Wb + j * WCP + e);
                    #pragma unroll
                    for (int i = 0; i < 5; i++) {
                        acc[i*5+j] = ffma2(av[i].x, bv.x, acc[i*5+j]);
                        acc[i*5+j] = ffma2(av[i].y, bv.y, acc[i*5+j]);
                    }
                }
            }
            #pragma unroll
            for (int m = 0; m < 25; m++) {
                acc[m] = fadd2(acc[m], __shfl_down_sync(0xffffffffu, acc[m], 4));
                acc[m] = fadd2(acc[m], __shfl_down_sync(0xffffffffu, acc[m], 2));
                acc[m] = fadd2(acc[m], __shfl_down_sync(0xffffffffu, acc[m], 1));
            }
            if (actR[r] && l8 == 0) {
                int ti = tiR[r], tj = tjR[r];
                #pragma unroll
                for (int i = 0; i < 5; i++)
                    #pragma unroll
                    for (int j = 0; j < 5; j++) {
                        float2 f = unpack2(acc[i*5+j]);
                        float v = f.x + f.y;
                        int lo = (ti*5+i) * HP + (tj*5+j);
                        if (c == 0) Hs[lo] = v; else Hs[lo] += v;
                        if (ti != tj) {
                            int up = (tj*5+j) * HP + (ti*5+i);
                            if (c == 0) Hs[up] = v; else Hs[up] += v;
                        }
                    }
            }
        }
        __syncthreads();
    }

    // ---- K = I + H*C; rhs col 65 = -H*u (fp64); col 64 = delta - H col64 ----
    for (int a = w; a < NA; a += 12) {
        const float* Hr = Hs + a * HP;
        double acc = 0.0;
        for (int k2 = lane; k2 < NA; k2 += 32) {
            float uk = (k2 < 64) ? ens[k2] : q;
            acc += (double)Hr[k2] * (double)uk;
        }
        #pragma unroll
        for (int off = 16; off; off >>= 1) acc += __shfl_down_sync(0xffffffffu, acc, off);
        if (lane == 0) Km[a * KP + 65] = (float)(-acc);
    }
    if (t < NA)
        Km[t * KP + 64] = ((t == 64) ? 1.0f : 0.0f) - Hs[t * HP + 64];
    {
        const int half = lane >> 4;
        const int c0 = (lane & 15) * 4;
        #pragma unroll
        for (int pass = 0; pass < 3; pass++) {
            int a = pass * 24 + w * 2 + half;
            if (a < NA) {
                const float* Hr = Hs + a * HP;
                ull acc0 = 0ull, acc1 = 0ull;
                #pragma unroll 4
                for (int k4 = 0; k4 < 16; k4++) {
                    float4 hv = *(const float4*)(Hr + k4 * 4);
                    ulonglong2 a0 = *(const ulonglong2*)(As + (k4*4+0) * 64 + c0);
                    ulonglong2 a1 = *(const ulonglong2*)(As + (k4*4+1) * 64 + c0);
                    ulonglong2 a2 = *(const ulonglong2*)(As + (k4*4+2) * 64 + c0);
                    ulonglong2 a3 = *(const ulonglong2*)(As + (k4*4+3) * 64 + c0);
                    ull h0 = dup2(hv.x), h1 = dup2(hv.y), h2 = dup2(hv.z), h3 = dup2(hv.w);
                    acc0 = ffma2(h0, a0.x, acc0); acc1 = ffma2(h0, a0.y, acc1);
                    acc0 = ffma2(h1, a1.x, acc0); acc1 = ffma2(h1, a1.y, acc1);
                    acc0 = ffma2(h2, a2.x, acc0); acc1 = ffma2(h2, a2.y, acc1);
                    acc0 = ffma2(h3, a3.x, acc0); acc1 = ffma2(h3, a3.y, acc1);
                }
                float2 f0 = unpack2(acc0), f1 = unpack2(acc1);
                float4 v;
                v.x = f0.x + ((a == c0+0) ? 1.0f : 0.0f);
                v.y = f0.y + ((a == c0+1) ? 1.0f : 0.0f);
                v.z = f1.x + ((a == c0+2) ? 1.0f : 0.0f);
                v.w = f1.y + ((a == c0+3) ? 1.0f : 0.0f);
                *(float4*)(Km + a * KP + c0) = v;
            }
        }
    }
    __syncthreads();

    // ---- Gauss-Jordan, register-resident columns, REDUX pivot select ----
    {
        const int cols0 = (w < 6) ? 6 : 5;
        float cv0[6], cv1[6], cv2[6];
        #pragma unroll
        for (int c = 0; c < 6; c++) {
            cv0[c] = 0.f; cv1[c] = 0.f; cv2[c] = 0.f;
            int j = w + 12 * c;
            if (c < cols0) {
                cv0[c] = Km[lane * KP + j];
                cv1[c] = Km[(lane + 32) * KP + j];
                if (lane == 0) cv2[c] = Km[64 * KP + j];
            }
        }
        bool piv0 = false, piv1 = false, piv2 = false;
        if (w == 0) {                           // publish col 0 + select pivot 0
            Fm[lane] = cv0[0];
            Fm[lane + 32] = cv1[0];
            if (lane == 0) Fm[64] = cv2[0];
            unsigned int key = pivkey(cv0[0], lane);
            unsigned int k1  = pivkey(cv1[0], lane + 32);
            if (k1 > key) key = k1;
            if (lane == 0) { unsigned int k2 = pivkey(cv2[0], 64); if (k2 > key) key = k2; }
            key = __reduce_max_sync(0xffffffffu, key);
            int prow = (int)(key & 0x7Fu);
            float src = (prow < 32) ? cv0[0] : ((prow < 64) ? cv1[0] : cv2[0]);
            float pval = __shfl_sync(0xffffffffu, src, prow & 31);
            if (lane == 0) { pivhist[0] = prow; dinv[0] = 1.0f / pval; }
        }
        __syncthreads();

        for (int k = 0; k < NA; k++) {
            int pk = pivhist[k];
            float dk = dinv[k];
            float m0 = Fm[k * FP + lane] * dk;
            float m1 = Fm[k * FP + lane + 32] * dk;
            float m2 = Fm[k * FP + 64] * dk;
            if (lane == pk)      { m0 = 0.f; piv0 = true; }
            if (lane + 32 == pk) { m1 = 0.f; piv1 = true; }
            if (pk == 64)        { m2 = 0.f; piv2 = true; }
            #pragma unroll
            for (int c = 0; c < 6; c++) {
                int j = w + 12 * c;
                if (c < cols0 && j > k) {       // warp-uniform predicate
                    float src = (pk < 32) ? cv0[c] : ((pk < 64) ? cv1[c] : cv2[c]);
                    float pv = __shfl_sync(0xffffffffu, src, pk & 31);
                    cv0[c] = fmaf(-m0, pv, cv0[c]);
                    cv1[c] = fmaf(-m1, pv, cv1[c]);
                    cv2[c] = fmaf(-m2, pv, cv2[c]);
                }
            }
            int nk = k + 1;
            if (nk < NA && w == (nk % 12)) {    // publish col nk + select pivot nk
                #pragma unroll
                for (int c = 0; c < 6; c++) {
                    if (c < cols0 && (w + 12 * c) == nk) {
                        float v0 = cv0[c], v1 = cv1[c], v2 = cv2[c];
                        Fm[nk * FP + lane] = v0;
                        Fm[nk * FP + lane + 32] = v1;
                        if (lane == 0) Fm[nk * FP + 64] = v2;
                        unsigned int key = piv0 ? 0u : pivkey(v0, lane);
                        unsigned int k1  = piv1 ? 0u : pivkey(v1, lane + 32);
                        if (k1 > key) key = k1;
                        if (lane == 0 && !piv2) {
                            unsigned int k2 = pivkey(v2, 64);
                            if (k2 > key) key = k2;
                        }
                        key = __reduce_max_sync(0xffffffffu, key);
                        int prow = (int)(key & 0x7Fu);
                        float src = (prow < 32) ? v0 : ((prow < 64) ? v1 : v2);
                        float pval = __shfl_sync(0xffffffffu, src, prow & 31);
                        if (lane == 0) { pivhist[nk] = prow; dinv[nk] = 1.0f / pval; }
                    }
                }
            }
            __syncthreads();
        }

        // rhs col 65 lives in warp 5 (c = 5): publish to rf
        if (w == 5) {
            rf[lane] = cv0[5];
            rf[lane + 32] = cv1[5];
            if (lane == 0) rf[64] = cv2[5];
        }
        __syncthreads();
    }

    // ---- direct solution (Jordan; no back-substitution, no refinement) ----
    if (t < NAT) out[mol * NAT + t] = rf[pivhist[t]] * dinv[t];
}

extern "C" void kernel_launch(void* const* d_in, const int* in_sizes, int n_in,
                              void* d_out, int out_size)
{
    const float* positions      = (const float*)d_in[0];
    const float* T              = (const float*)d_in[1];
    const float* eneg           = (const float*)d_in[2];
    const float* node_attrs     = (const float*)d_in[3];
    const float* total_charge   = (const float*)d_in[4];
    const float* hardness       = (const float*)d_in[6];
    const float* cov_radii      = (const float*)d_in[7];
    const int*   atomic_numbers = (const int*)d_in[8];
    const int*   edge_index     = (const int*)d_in[9];
    float* out = (float*)d_out;

    int B = in_sizes[4];
    cudaFuncSetAttribute(cheq_kernel, cudaFuncAttributeMaxDynamicSharedMemorySize, SMEM_BYTES);
    cheq_kernel<<<B, NTH, SMEM_BYTES>>>(positions, T, eneg, node_attrs, total_charge,
                                        hardness, cov_radii, atomic_numbers, edge_index, out);
}

// round 17
// speedup vs baseline: 1.1296x; 1.0236x over previous
#include <cuda_runtime.h>
#include <math.h>

typedef unsigned long long ull;

constexpr int NAT = 64;
constexpr int NE  = 512;
constexpr int NA  = 65;
constexpr int NUMEL = 10;
constexpr int CH  = 256;    // chunk width (edges)
constexpr int WCP = 260;    // Wc pitch (floats)
constexpr int HP  = 68;     // Hs pitch
constexpr int KP  = 68;     // Km pitch (16B-aligned rows)
constexpr int FP  = 68;     // Fm pitch
constexpr int NTH = 384;    // 12 warps

// ---- shared memory byte offsets ----
constexpr int OFF_WC  = 0;                       // float Wc[65][260]
constexpr int OFF_KM  = OFF_WC;                  // float Km[65][68]  (aliases Wc)
constexpr int OFF_FM  = OFF_WC + 65*KP*4 + 16;   // float Fm[65][68]  (aliases Wc, after Km)
constexpr int OFF_AS  = OFF_WC + 65*WCP*4;       // float As[64][64]
constexpr int OFF_HS  = OFF_AS + 64*64*4;        // float Hs[65][68]
constexpr int OFF_SA  = OFF_HS + 65*HP*4;        // float sa[512]
constexpr int OFF_PX  = OFF_SA + 2048;
constexpr int OFF_PY  = OFF_PX + 256;
constexpr int OFF_PZ  = OFF_PY + 256;
constexpr int OFF_EN  = OFF_PZ + 256;
constexpr int OFF_DG  = OFF_EN + 256;
constexpr int OFF_RR  = OFF_DG + 256;
constexpr int OFF_RF  = OFF_RR + 256;            // float rf[68]
constexpr int OFF_DI  = OFF_RF + 272;            // float dinv[68]
constexpr int OFF_PH  = OFF_DI + 272;            // int pivhist[68] (doubles as ready-flag)
constexpr int SMEM_BYTES = OFF_PH + 272;         // ~104 KB -> 2 CTAs/SM

static_assert(OFF_FM + 65*FP*4 <= OFF_AS, "Fm must fit in Wc region after Km");

__device__ __forceinline__ ull ffma2(ull a, ull b, ull c) {
    ull d; asm("fma.rn.f32x2 %0, %1, %2, %3;" : "=l"(d) : "l"(a), "l"(b), "l"(c)); return d;
}
__device__ __forceinline__ ull fadd2(ull a, ull b) {
    ull d; asm("add.rn.f32x2 %0, %1, %2;" : "=l"(d) : "l"(a), "l"(b)); return d;
}
__device__ __forceinline__ float2 unpack2(ull v) {
    float2 f; asm("mov.b64 {%0,%1}, %2;" : "=f"(f.x), "=f"(f.y) : "l"(v)); return f;
}
__device__ __forceinline__ ull dup2(float f) {
    ull d; asm("mov.b64 %0, {%1, %1};" : "=l"(d) : "f"(f)); return d;
}
// monotone packed key: |v| in top 25 bits, row in low 7
__device__ __forceinline__ unsigned int pivkey(float v, int row) {
    return (__float_as_uint(fabsf(v)) & 0xFFFFFF80u) | (unsigned int)row;
}
__device__ __forceinline__ int ld_acq(const int* p) {
    int v; asm volatile("ld.acquire.cta.b32 %0, [%1];" : "=r"(v) : "l"(p) : "memory"); return v;
}
__device__ __forceinline__ void st_rel(int* p, int v) {
    asm volatile("st.release.cta.b32 [%0], %1;" :: "l"(p), "r"(v) : "memory");
}

__global__ __launch_bounds__(NTH, 2)
void cheq_kernel(const float* __restrict__ positions,
                 const float* __restrict__ T,
                 const float* __restrict__ eneg,
                 const float* __restrict__ node_attrs,
                 const float* __restrict__ total_charge,
                 const float* __restrict__ hardness,
                 const float* __restrict__ cov_radii,
                 const int*   __restrict__ atomic_numbers,
                 const int*   __restrict__ edge_index,
                 float* __restrict__ out)
{
    extern __shared__ __align__(16) unsigned char sm[];
    float* Wc  = (float*)(sm + OFF_WC);
    float* Km  = (float*)(sm + OFF_KM);
    float* Fm  = (float*)(sm + OFF_FM);
    float* As  = (float*)(sm + OFF_AS);
    float* Hs  = (float*)(sm + OFF_HS);
    float* sa  = (float*)(sm + OFF_SA);
    float* px  = (float*)(sm + OFF_PX);
    float* py  = (float*)(sm + OFF_PY);
    float* pz  = (float*)(sm + OFF_PZ);
    float* ens = (float*)(sm + OFF_EN);
    float* dgs = (float*)(sm + OFF_DG);
    float* rrs = (float*)(sm + OFF_RR);
    float* rf  = (float*)(sm + OFF_RF);
    float* dinv= (float*)(sm + OFF_DI);
    int*   pivhist = (int*)(sm + OFF_PH);

    const int mol = blockIdx.x;
    const int t = threadIdx.x;
    const int lane = t & 31;
    const int w = t >> 5;
    const float* Tm = T + (size_t)mol * (NAT * NE);
    const float* pm = positions + mol * NAT * 3;
    const int* eim = edge_index + mol * 2 * NE;
    const float q = total_charge[mol];

    // ---- per-atom small loads + pivhist flag init ----
    if (t < NAT) {
        px[t] = pm[3*t+0]; py[t] = pm[3*t+1]; pz[t] = pm[3*t+2];
        ens[t] = eneg[mol * NAT + t];
        float r = cov_radii[atomic_numbers[mol * NAT + t]];
        rrs[t] = r * r;
        const float* na = node_attrs + (size_t)(mol * NAT + t) * NUMEL;
        float best = na[0]; int bi = 0;
        #pragma unroll
        for (int j = 1; j < NUMEL; j++) { float v = na[j]; if (v > best) { best = v; bi = j; } }
        dgs[t] = hardness[bi] + 0.5641895835477563f / r;
    }
    if (t < 68) pivhist[t] = -1;
    __syncthreads();

    // ---- A matrix (64x64, symmetric): lower triangle only, mirrored store ----
    for (int p = t; p < 2080; p += NTH) {        // 2080 = 64*65/2
        int i = (int)((sqrtf(8.0f * p + 1.0f) - 1.0f) * 0.5f);
        while ((i + 1) * (i + 2) / 2 <= p) ++i;
        while (i * (i + 1) / 2 > p) --i;
        int j = p - i * (i + 1) / 2;
        float v;
        if (i == j) v = dgs[i];
        else {
            float dx = px[i]-px[j], dy = py[i]-py[j], dz = pz[i]-pz[j];
            float d = sqrtf(dx*dx + dy*dy + dz*dz);
            float arg = d * rsqrtf(2.0f * (rrs[i] + rrs[j]));
            v = erff(arg) / d;
        }
        As[i * 64 + j] = v;
        As[j * 64 + i] = v;
    }

    // ---- edges: sa[e] = sqrt(1/cut), cancellation-free ----
    for (int e = t; e < NE; e += NTH) {
        int a0 = eim[e], a1 = eim[NE + e];
        float dx = px[a0]-px[a1], dy = py[a0]-py[a1], dz = pz[a0]-pz[a1];
        float ed = sqrtf(dx*dx + dy*dy + dz*dz);
        float th = 0.15707963267948966f * ed;
        float sh = sinf(0.5f * th);
        float ct = cosf(th);
        float dv = ct / (2.0f * sh * sh);
        dv = fmaxf(dv, 1e-30f);
        sa[e] = sqrtf(dv);
    }
    __syncthreads();

    // ---- syrk tile geometry (91 triangular 5x5 tiles; 12 warps x 4 groups x 2 rounds) ----
    const int g  = (lane >> 3);
    const int l8 = lane & 7;
    int tiR[2], tjR[2]; bool actR[2];
    #pragma unroll
    for (int r = 0; r < 2; r++) {
        int p = r * 48 + w * 4 + g;
        actR[r] = (p < 91);
        int pp = actR[r] ? p : 0;
        int ti = (int)((sqrtf(8.0f * pp + 1.0f) - 1.0f) * 0.5f);
        while ((ti + 1) * (ti + 2) / 2 <= pp) ++ti;
        while (ti * (ti + 1) / 2 > pp) --ti;
        tiR[r] = ti; tjR[r] = pp - ti * (ti + 1) / 2;
    }

    // ---- chunk loop: H = W W^T ----
    for (int c = 0; c < 2; c++) {
        const int base = c * CH;
        for (int idx = t; idx < 64 * 64; idx += NTH) {
            int a = idx >> 6, e = (idx & 63) * 4;
            float4 v  = *(const float4*)(Tm + a * NE + base + e);
            float4 s4 = *(const float4*)(sa + base + e);
            v.x *= s4.x; v.y *= s4.y; v.z *= s4.z; v.w *= s4.w;
            *(float4*)(Wc + a * WCP + e) = v;
        }
        if (t < 64) *(float4*)(Wc + 64 * WCP + 4*t) = *(const float4*)(sa + base + 4*t);
        __syncthreads();

        #pragma unroll
        for (int r = 0; r < 2; r++) {
            const float* Wa = Wc + (tiR[r] * 5) * WCP;
            const float* Wb = Wc + (tjR[r] * 5) * WCP;
            const bool diag = (tiR[r] == tjR[r]);
            ull acc[25];
            #pragma unroll
            for (int m = 0; m < 25; m++) acc[m] = 0ull;
            for (int e = 4 * l8; e < CH; e += 32) {
                ulonglong2 av[5];
                #pragma unroll
                for (int i = 0; i < 5; i++)
                    av[i] = *(const ulonglong2*)(Wa + i * WCP + e);
                #pragma unroll
                for (int j = 0; j < 5; j++) {
                    ulonglong2 bv = diag ? av[j] : *(const ulonglong2*)(Wb + j * WCP + e);
                    #pragma unroll
                    for (int i = 0; i < 5; i++) {
                        acc[i*5+j] = ffma2(av[i].x, bv.x, acc[i*5+j]);
                        acc[i*5+j] = ffma2(av[i].y, bv.y, acc[i*5+j]);
                    }
                }
            }
            #pragma unroll
            for (int m = 0; m < 25; m++) {
                acc[m] = fadd2(acc[m], __shfl_down_sync(0xffffffffu, acc[m], 4));
                acc[m] = fadd2(acc[m], __shfl_down_sync(0xffffffffu, acc[m], 2));
                acc[m] = fadd2(acc[m], __shfl_down_sync(0xffffffffu, acc[m], 1));
            }
            if (actR[r] && l8 == 0) {
                int ti = tiR[r], tj = tjR[r];
                #pragma unroll
                for (int i = 0; i < 5; i++)
                    #pragma unroll
                    for (int j = 0; j < 5; j++) {
                        float2 f = unpack2(acc[i*5+j]);
                        float v = f.x + f.y;
                        int lo = (ti*5+i) * HP + (tj*5+j);
                        if (c == 0) Hs[lo] = v; else Hs[lo] += v;
                        if (ti != tj) {
                            int up = (tj*5+j) * HP + (ti*5+i);
                            if (c == 0) Hs[up] = v; else Hs[up] += v;
                        }
                    }
            }
        }
        __syncthreads();
    }

    // ---- K = I + H*C; rhs col 65 = -H*u (fp64); col 64 = delta - H col64 ----
    for (int a = w; a < NA; a += 12) {
        const float* Hr = Hs + a * HP;
        double acc = 0.0;
        for (int k2 = lane; k2 < NA; k2 += 32) {
            float uk = (k2 < 64) ? ens[k2] : q;
            acc += (double)Hr[k2] * (double)uk;
        }
        #pragma unroll
        for (int off = 16; off; off >>= 1) acc += __shfl_down_sync(0xffffffffu, acc, off);
        if (lane == 0) Km[a * KP + 65] = (float)(-acc);
    }
    if (t < NA)
        Km[t * KP + 64] = ((t == 64) ? 1.0f : 0.0f) - Hs[t * HP + 64];
    {
        const int half = lane >> 4;
        const int c0 = (lane & 15) * 4;
        #pragma unroll
        for (int pass = 0; pass < 3; pass++) {
            int a = pass * 24 + w * 2 + half;
            if (a < NA) {
                const float* Hr = Hs + a * HP;
                ull acc0 = 0ull, acc1 = 0ull;
                #pragma unroll 4
                for (int k4 = 0; k4 < 16; k4++) {
                    float4 hv = *(const float4*)(Hr + k4 * 4);
                    ulonglong2 a0 = *(const ulonglong2*)(As + (k4*4+0) * 64 + c0);
                    ulonglong2 a1 = *(const ulonglong2*)(As + (k4*4+1) * 64 + c0);
                    ulonglong2 a2 = *(const ulonglong2*)(As + (k4*4+2) * 64 + c0);
                    ulonglong2 a3 = *(const ulonglong2*)(As + (k4*4+3) * 64 + c0);
                    ull h0 = dup2(hv.x), h1 = dup2(hv.y), h2 = dup2(hv.z), h3 = dup2(hv.w);
                    acc0 = ffma2(h0, a0.x, acc0); acc1 = ffma2(h0, a0.y, acc1);
                    acc0 = ffma2(h1, a1.x, acc0); acc1 = ffma2(h1, a1.y, acc1);
                    acc0 = ffma2(h2, a2.x, acc0); acc1 = ffma2(h2, a2.y, acc1);
                    acc0 = ffma2(h3, a3.x, acc0); acc1 = ffma2(h3, a3.y, acc1);
                }
                float2 f0 = unpack2(acc0), f1 = unpack2(acc1);
                float4 v;
                v.x = f0.x + ((a == c0+0) ? 1.0f : 0.0f);
                v.y = f0.y + ((a == c0+1) ? 1.0f : 0.0f);
                v.z = f1.x + ((a == c0+2) ? 1.0f : 0.0f);
                v.w = f1.y + ((a == c0+3) ? 1.0f : 0.0f);
                *(float4*)(Km + a * KP + c0) = v;
            }
        }
    }
    __syncthreads();

    // ---- Gauss-Jordan, flag-synced producer/consumer (no block barriers) ----
    // pivhist[k] is both pivot index and ready-flag (preinit -1). Owner of col
    // k+1 updates+publishes it FIRST, then finishes its other columns; all
    // warps slide freely behind the producer chain.
    {
        const int cols0 = (w < 6) ? 6 : 5;
        float cv0[6], cv1[6], cv2[6];
        #pragma unroll
        for (int c = 0; c < 6; c++) {
            cv0[c] = 0.f; cv1[c] = 0.f; cv2[c] = 0.f;
            int j = w + 12 * c;
            if (c < cols0) {
                cv0[c] = Km[lane * KP + j];
                cv1[c] = Km[(lane + 32) * KP + j];
                if (lane == 0) cv2[c] = Km[64 * KP + j];
            }
        }
        bool piv0 = false, piv1 = false, piv2 = false;
        if (w == 0) {                           // bootstrap: publish col 0 + pivot 0
            Fm[lane] = cv0[0];
            Fm[lane + 32] = cv1[0];
            if (lane == 0) Fm[64] = cv2[0];
            unsigned int key = pivkey(cv0[0], lane);
            unsigned int k1  = pivkey(cv1[0], lane + 32);
            if (k1 > key) key = k1;
            if (lane == 0) { unsigned int k2 = pivkey(cv2[0], 64); if (k2 > key) key = k2; }
            key = __reduce_max_sync(0xffffffffu, key);
            int prow = (int)(key & 0x7Fu);
            float src = (prow < 32) ? cv0[0] : ((prow < 64) ? cv1[0] : cv2[0]);
            float pval = __shfl_sync(0xffffffffu, src, prow & 31);
            if (lane == 0) dinv[0] = 1.0f / pval;
            __syncwarp();
            if (lane == 0) st_rel(&pivhist[0], prow);
        }

        for (int k = 0; k < NA; k++) {
            int pk;
            do { pk = ld_acq(&pivhist[k]); } while (pk < 0);
            float dk = dinv[k];
            float m0 = Fm[k * FP + lane] * dk;
            float m1 = Fm[k * FP + lane + 32] * dk;
            float m2 = Fm[k * FP + 64] * dk;
            if (lane == pk)      { m0 = 0.f; piv0 = true; }
            if (lane + 32 == pk) { m1 = 0.f; piv1 = true; }
            if (pk == 64)        { m2 = 0.f; piv2 = true; }
            int nk = k + 1;
            bool owner = (nk < NA) && (w == (nk % 12));
            if (owner) {                         // publish-first
                #pragma unroll
                for (int c = 0; c < 6; c++) {
                    if (c < cols0 && (w + 12 * c) == nk) {
                        float src = (pk < 32) ? cv0[c] : ((pk < 64) ? cv1[c] : cv2[c]);
                        float pv = __shfl_sync(0xffffffffu, src, pk & 31);
                        float v0 = fmaf(-m0, pv, cv0[c]);
                        float v1 = fmaf(-m1, pv, cv1[c]);
                        float v2 = fmaf(-m2, pv, cv2[c]);
                        cv0[c] = v0; cv1[c] = v1; cv2[c] = v2;
                        Fm[nk * FP + lane] = v0;
                        Fm[nk * FP + lane + 32] = v1;
                        if (lane == 0) Fm[nk * FP + 64] = v2;
                        unsigned int key = piv0 ? 0u : pivkey(v0, lane);
                        unsigned int k1  = piv1 ? 0u : pivkey(v1, lane + 32);
                        if (k1 > key) key = k1;
                        if (lane == 0 && !piv2) {
                            unsigned int k2 = pivkey(v2, 64);
                            if (k2 > key) key = k2;
                        }
                        key = __reduce_max_sync(0xffffffffu, key);
                        int prow = (int)(key & 0x7Fu);
                        float src2 = (prow < 32) ? v0 : ((prow < 64) ? v1 : v2);
                        float pval = __shfl_sync(0xffffffffu, src2, prow & 31);
                        if (lane == 0) dinv[nk] = 1.0f / pval;
                        __syncwarp();
                        if (lane == 0) st_rel(&pivhist[nk], prow);
                    }
                }
            }
            #pragma unroll
            for (int c = 0; c < 6; c++) {
                int j = w + 12 * c;
                bool skip = owner && (j == nk);
                if (c < cols0 && j > k && !skip) {  // warp-uniform predicate
                    float src = (pk < 32) ? cv0[c] : ((pk < 64) ? cv1[c] : cv2[c]);
                    float pv = __shfl_sync(0xffffffffu, src, pk & 31);
                    cv0[c] = fmaf(-m0, pv, cv0[c]);
                    cv1[c] = fmaf(-m1, pv, cv1[c]);
                    cv2[c] = fmaf(-m2, pv, cv2[c]);
                }
            }
        }

        // rhs col 65 lives in warp 5 (c = 5): publish to rf
        if (w == 5) {
            rf[lane] = cv0[5];
            rf[lane + 32] = cv1[5];
            if (lane == 0) rf[64] = cv2[5];
        }
        __syncthreads();
    }

    // ---- direct solution (Jordan; no back-substitution, no refinement) ----
    if (t < NAT) out[mol * NAT + t] = rf[pivhist[t]] * dinv[t];
}

extern "C" void kernel_launch(void* const* d_in, const int* in_sizes, int n_in,
                              void* d_out, int out_size)
{
    const float* positions      = (const float*)d_in[0];
    const float* T              = (const float*)d_in[1];
    const float* eneg           = (const float*)d_in[2];
    const float* node_attrs     = (const float*)d_in[3];
    const float* total_charge   = (const float*)d_in[4];
    const float* hardness       = (const float*)d_in[6];
    const float* cov_radii      = (const float*)d_in[7];
    const int*   atomic_numbers = (const int*)d_in[8];
    const int*   edge_index     = (const int*)d_in[9];
    float* out = (float*)d_out;

    int B = in_sizes[4];
    cudaFuncSetAttribute(cheq_kernel, cudaFuncAttributeMaxDynamicSharedMemorySize, SMEM_BYTES);
    cheq_kernel<<<B, NTH, SMEM_BYTES>>>(positions, T, eneg, node_attrs, total_charge,
                                        hardness, cov_radii, atomic_numbers, edge_index, out);
}